// round 14
// baseline (speedup 1.0000x reference)
#include <cuda_runtime.h>
#include <cuda_bf16.h>

// PointGNN, algebraically reduced, single persistent kernel, 1 block/SM.
//   adj(i) = { j : |x_i - x_j|^2 < 0.05 }  (fixed; self always in-set)
//   F_t[j]   = MLP_f([0,0,0,state_j])      (per NODE, not per edge)
//   agg_t[i] = max_{j in adj(i)} F_t[j]    (channelwise; F>=0 so 0-floor exact)
//   state   += relu(MLP_g(agg_t))
// h-MLP provably dead. NEW: one-time cooperative transpose of all weights into
// padded column-major global buffers (stride 132/68 words -> conflict-free
// LDS.128 for per-thread weight columns); activations read as warp-uniform
// float4 broadcasts. Neighbor lists hold pre-scaled byte offsets. 4 grid bars.
// GRID=128 <= 148 SMs -> 1 co-resident block/SM: barrier deadlock-free.

#define MM    384
#define NODES (4*MM)
#define MASKW 12
#define BN    12
#define TPB   384
#define GRID  (NODES/BN)   // 128
#define MAXD  128

// smem layout (float offsets)
#define OFF_G1T 0        // 64*132  = 8448   gW1^T [k64][d]
#define OFF_G2T 8448     // 32*68   = 2176   gW2^T [k2][d]
#define OFF_F2T 10624    // 128*68  = 8704   fW2^T [c][kk]
#define OFF_F3T 19328    // 128*132 = 16896  fW3^T [c][kk]
#define OFF_A   36224    // 12*128
#define OFF_B   37760    // 12*128
#define OFF_G3  39296    // 96
#define OFF_N   39392    // 12*128 u32 (byte offsets)
#define OFF_D   40928    // 12 int
#define SMEM_BYTES (40940*4)   // 163,760 B < 227KB opt-in max

__device__ float    g_Fbuf[2][NODES * 128];
__device__ unsigned g_bar;        // monotonic; wrap-safe barrier
__device__ float    g_G1t[3][8448];
__device__ float    g_G2t[3][2176];
__device__ float    g_F2t[3][8704];
__device__ float    g_F3t[3][16896];

__device__ __forceinline__ void cpa(float* dst, const float* src, int nfloats) {
    for (int idx = threadIdx.x * 4; idx < nfloats; idx += TPB * 4) {
        unsigned sa = (unsigned)__cvta_generic_to_shared(dst + idx);
        asm volatile("cp.async.cg.shared.global [%0], [%1], 16;"
                     :: "r"(sa), "l"(src + idx));
    }
}
__device__ __forceinline__ void cpa_commit() {
    asm volatile("cp.async.commit_group;");
}
template<int N> __device__ __forceinline__ void cpa_wait() {
    asm volatile("cp.async.wait_group %0;" :: "n"(N));
}

// grid-wide barrier: monotonic ticket counter, wrap-safe compare
__device__ __forceinline__ void grid_bar() {
    __syncthreads();
    if (threadIdx.x == 0) {
        __threadfence();
        unsigned v = atomicAdd(&g_bar, 1u);
        unsigned target = v - (v % (unsigned)GRID) + (unsigned)GRID;
        unsigned cur;
        do {
            asm volatile("ld.acquire.gpu.u32 %0, [%1];" : "=r"(cur) : "l"(&g_bar));
        } while ((int)(cur - target) < 0);
    }
    __syncthreads();
}

// ---------------------------------------------------------------------------
__global__ __launch_bounds__(TPB) void pointgnn_persistent(
    const float* x, float* state,
    const float* fW1, const float* fb1, const float* fW2, const float* fb2,
    const float* fW3, const float* fb3,
    const float* gW1, const float* gb1, const float* gW2, const float* gb2,
    const float* gW3, const float* gb3)
{
    extern __shared__ float sm[];
    float*    sG1t = sm + OFF_G1T;
    float*    sG2t = sm + OFF_G2T;
    float*    sF2t = sm + OFF_F2T;
    float*    sF3t = sm + OFF_F3T;
    float*    sA   = sm + OFF_A;
    float*    sB   = sm + OFF_B;
    float*    sG3  = sm + OFF_G3;
    unsigned* sN32 = (unsigned*)(sm + OFF_N);
    int*      sD   = (int*)(sm + OFF_D);

    const int t    = threadIdx.x;
    const int base = blockIdx.x * BN;        // 12 nodes, same batch (384%12==0)
    const int n    = base / MM;
    const int c    = t & 127;                // channel lane
    const int g3c  = t >> 7;                 // 0..2 -> node quad
    const int k64  = t & 63;
    const int h6   = t >> 6;                 // 0..5 -> node pair

    // ---- one-time prefetch: all 3 steps' biases + state + fW1 rows ----
    float bf1[3], bf2[3], bf3[3], bg1[3], bg2[3], bg3s[3];
    float w1a[3], w1b[3], w1c[3];
    #pragma unroll
    for (int s = 0; s < 3; s++) {
        bf1[s] = fb1[s*64  + k64];
        bf2[s] = fb2[s*128 + c];
        bf3[s] = fb3[s*128 + c];
        bg1[s] = gb1[s*64  + k64];
        bg2[s] = gb2[s*32  + (t & 31)];
        w1a[s] = fW1[s*384 + 3*64 + k64];
        w1b[s] = fW1[s*384 + 4*64 + k64];
        w1c[s] = fW1[s*384 + 5*64 + k64];
    }
    float stv = 0.f;
    if (t < BN*3) {
        stv = x[base*3 + t];
        #pragma unroll
        for (int s = 0; s < 3; s++) bg3s[s] = gb3[s*3 + t % 3];
    }

    // ---- cooperative weight transpose into padded global buffers ----
    {
        const int stride = GRID * TPB;
        const int idx0 = blockIdx.x * TPB + t;
        for (int idx = idx0; idx < 3*64*128; idx += stride) {   // fW2 [s][k][c]
            int s = idx >> 13, r = idx & 8191, k = r >> 7, cc = r & 127;
            g_F2t[s][cc*68 + k] = fW2[idx];
        }
        for (int idx = idx0; idx < 3*128*128; idx += stride) {  // fW3 [s][k][c]
            int s = idx >> 14, r = idx & 16383, k = r >> 7, cc = r & 127;
            g_F3t[s][cc*132 + k] = fW3[idx];
        }
        for (int idx = idx0; idx < 3*128*64; idx += stride) {   // gW1 [s][d][k]
            int s = idx >> 13, r = idx & 8191, d = r >> 6, k = r & 63;
            g_G1t[s][k*132 + d] = gW1[idx];
        }
        for (int idx = idx0; idx < 3*64*32; idx += stride) {    // gW2 [s][d][k]
            int s = idx >> 11, r = idx & 2047, d = r >> 5, k = r & 31;
            g_G2t[s][k*68 + d] = gW2[idx];
        }
    }

    // ---- adjacency (once): warp-per-node popc compaction, pre-scaled byte
    //      offsets (j*512); lists padded to MAXD with self (exact under max) ----
    {
        const int warp = t >> 5, lane = t & 31;   // 12 warps = 12 nodes
        const int i = base + warp;
        float xi0 = x[i*3+0], xi1 = x[i*3+1], xi2 = x[i*3+2];
        int cnt = 0;
        #pragma unroll
        for (int wc = 0; wc < MASKW; wc++) {
            int j = wc*32 + lane;
            const float* xj = x + (n*MM + j)*3;
            float dx = xi0 - xj[0], dy = xi1 - xj[1], dz = xi2 - xj[2];
            // non-contracted to match reference's (diff*diff).sum() compare
            float s2 = __fadd_rn(__fadd_rn(__fmul_rn(dx,dx), __fmul_rn(dy,dy)),
                                 __fmul_rn(dz,dz));
            bool pred = s2 < 0.05f;
            unsigned m = __ballot_sync(0xffffffffu, pred);
            int pos = cnt + __popc(m & ((1u << lane) - 1u));
            if (pred && pos < MAXD) sN32[warp*MAXD + pos] = (unsigned)(j*512);
            cnt += __popc(m);
        }
        int cl = cnt < MAXD ? cnt : MAXD;
        unsigned selfoff = (unsigned)((i - n*MM)*512);
        for (int p = cl + lane; p < MAXD; p += 32) sN32[warp*MAXD + p] = selfoff;
        if (lane == 0) sD[warp] = (cl + 7) & ~7;
    }
    if (t < BN*3) sB[(t/3)*128 + t%3] = stv;       // state := x
    grid_bar();   // transposed weights ready everywhere; sN/sB ready in-block

    // ---- stage f0 transposed weights ----
    cpa(sF2t, g_F2t[0], 8704);  cpa_commit();
    cpa(sF3t, g_F3t[0], 16896); cpa_commit();

    // ================= F0 = MLP_f(x) =================
    {
        // layer1 (rows 3..5 only, weights in regs)
        #pragma unroll
        for (int j = 0; j < 2; j++) {
            int i = h6*2 + j;
            float acc = bf1[0];
            acc = fmaf(sB[i*128+0], w1a[0], acc);
            acc = fmaf(sB[i*128+1], w1b[0], acc);
            acc = fmaf(sB[i*128+2], w1c[0], acc);
            sA[i*128 + k64] = fmaxf(acc, 0.f);
        }
        cpa_wait<1>();        // F2t staged
        __syncthreads();

        // layer2: 64 -> 128, float4 weights + broadcast float4 acts, ILP-4
        float acc2[4];
        #pragma unroll
        for (int j = 0; j < 4; j++) acc2[j] = bf2[0];
        {
            const float* Wc = sF2t + c*68;
            #pragma unroll 4
            for (int kk = 0; kk < 64; kk += 4) {
                float4 w = *(const float4*)(Wc + kk);
                #pragma unroll
                for (int j = 0; j < 4; j++) {
                    float4 v = *(const float4*)(sA + (g3c*4 + j)*128 + kk);
                    acc2[j] = fmaf(v.x, w.x, acc2[j]);
                    acc2[j] = fmaf(v.y, w.y, acc2[j]);
                    acc2[j] = fmaf(v.z, w.z, acc2[j]);
                    acc2[j] = fmaf(v.w, w.w, acc2[j]);
                }
            }
        }
        #pragma unroll
        for (int j = 0; j < 4; j++) sB[(g3c*4 + j)*128 + c] = fmaxf(acc2[j], 0.f);
        cpa_wait<0>();        // F3t staged
        __syncthreads();

        // layer3: 128 -> 128, float4 weights + broadcast float4 acts, ILP-4
        float acc3[4];
        #pragma unroll
        for (int j = 0; j < 4; j++) acc3[j] = bf3[0];
        {
            const float* Wc = sF3t + c*132;
            #pragma unroll 4
            for (int kk = 0; kk < 128; kk += 4) {
                float4 w = *(const float4*)(Wc + kk);
                #pragma unroll
                for (int j = 0; j < 4; j++) {
                    float4 v = *(const float4*)(sB + (g3c*4 + j)*128 + kk);
                    acc3[j] = fmaf(v.x, w.x, acc3[j]);
                    acc3[j] = fmaf(v.y, w.y, acc3[j]);
                    acc3[j] = fmaf(v.z, w.z, acc3[j]);
                    acc3[j] = fmaf(v.w, w.w, acc3[j]);
                }
            }
        }
        float* F0 = g_Fbuf[0] + base*128;
        #pragma unroll
        for (int j = 0; j < 4; j++)
            F0[(g3c*4 + j)*128 + c] = fmaxf(acc3[j], 0.f);
    }
    grid_bar();

    // ================= 3 timesteps =================
    int cur = 0;
    #pragma unroll
    for (int s = 0; s < 3; s++) {
        // stage this step's transposed weights in the background
        cpa(sG1t, g_G1t[s], 8448);
        cpa(sG2t, g_G2t[s], 2176);
        cpa_commit();                               // group G
        if (s < 2) {
            cpa(sF2t, g_F2t[s+1], 8704);  cpa_commit();   // group F2
            cpa(sF3t, g_F3t[s+1], 16896); cpa_commit();   // group F3
        }
        if (t < 96) sG3[t] = gW3[s*96 + t];

        // phase A: channelwise max, 4 nodes interleaved, byte-offset addressing
        {
            const char* FnC = (const char*)(g_Fbuf[cur] + n*MM*128) + c*4;
            const int i0 = g3c*4;
            int dgq = sD[i0];
            dgq = max(dgq, sD[i0+1]); dgq = max(dgq, sD[i0+2]); dgq = max(dgq, sD[i0+3]);
            float mx[4] = {0.f, 0.f, 0.f, 0.f};
            for (int d = 0; d < dgq; d += 8) {
                float v[4][8];
                #pragma unroll
                for (int j = 0; j < 4; j++) {
                    const unsigned* Ni = sN32 + (i0 + j)*MAXD + d;
                    #pragma unroll
                    for (int e = 0; e < 8; e++)
                        v[j][e] = *(const float*)(FnC + Ni[e]);
                }
                #pragma unroll
                for (int j = 0; j < 4; j++) {
                    float m01 = fmaxf(v[j][0], v[j][1]), m23 = fmaxf(v[j][2], v[j][3]);
                    float m45 = fmaxf(v[j][4], v[j][5]), m67 = fmaxf(v[j][6], v[j][7]);
                    mx[j] = fmaxf(mx[j], fmaxf(fmaxf(m01, m23), fmaxf(m45, m67)));
                }
            }
            #pragma unroll
            for (int j = 0; j < 4; j++) sA[(i0 + j)*128 + c] = mx[j];
        }
        if (s < 2) cpa_wait<2>(); else cpa_wait<0>();   // g-weights staged
        __syncthreads();

        // phase B: g layer1 (128 -> 64), 2 nodes x 2 split-k, float4
        {
            float a0A = bg1[s], a0B = 0.f, a1A = bg1[s], a1B = 0.f;
            const float* A0 = sA + (h6*2)*128, * A1 = A0 + 128;
            const float* Wk = sG1t + k64*132;
            #pragma unroll 4
            for (int dd = 0; dd < 64; dd += 4) {
                float4 wA  = *(const float4*)(Wk + dd);
                float4 wB  = *(const float4*)(Wk + dd + 64);
                float4 vA0 = *(const float4*)(A0 + dd);
                float4 vB0 = *(const float4*)(A0 + dd + 64);
                float4 vA1 = *(const float4*)(A1 + dd);
                float4 vB1 = *(const float4*)(A1 + dd + 64);
                a0A = fmaf(vA0.x, wA.x, a0A); a0A = fmaf(vA0.y, wA.y, a0A);
                a0A = fmaf(vA0.z, wA.z, a0A); a0A = fmaf(vA0.w, wA.w, a0A);
                a0B = fmaf(vB0.x, wB.x, a0B); a0B = fmaf(vB0.y, wB.y, a0B);
                a0B = fmaf(vB0.z, wB.z, a0B); a0B = fmaf(vB0.w, wB.w, a0B);
                a1A = fmaf(vA1.x, wA.x, a1A); a1A = fmaf(vA1.y, wA.y, a1A);
                a1A = fmaf(vA1.z, wA.z, a1A); a1A = fmaf(vA1.w, wA.w, a1A);
                a1B = fmaf(vB1.x, wB.x, a1B); a1B = fmaf(vB1.y, wB.y, a1B);
                a1B = fmaf(vB1.z, wB.z, a1B); a1B = fmaf(vB1.w, wB.w, a1B);
            }
            sB[(h6*2    )*128 + k64] = fmaxf(a0A + a0B, 0.f);
            sB[(h6*2 + 1)*128 + k64] = fmaxf(a1A + a1B, 0.f);
        }
        __syncthreads();

        // phase C: g layer2 (64 -> 32), 1 output/thread, split-2, float4
        {
            int k2 = t & 31, i12 = t >> 5;
            float aA = bg2[s], aB = 0.f;
            const float* Bi = sB + i12*128;
            const float* Wk = sG2t + k2*68;
            #pragma unroll
            for (int dd = 0; dd < 32; dd += 4) {
                float4 wA = *(const float4*)(Wk + dd);
                float4 wB = *(const float4*)(Wk + dd + 32);
                float4 vA = *(const float4*)(Bi + dd);
                float4 vB = *(const float4*)(Bi + dd + 32);
                aA = fmaf(vA.x, wA.x, aA); aA = fmaf(vA.y, wA.y, aA);
                aA = fmaf(vA.z, wA.z, aA); aA = fmaf(vA.w, wA.w, aA);
                aB = fmaf(vB.x, wB.x, aB); aB = fmaf(vB.y, wB.y, aB);
                aB = fmaf(vB.z, wB.z, aB); aB = fmaf(vB.w, wB.w, aB);
            }
            sA[i12*128 + k2] = fmaxf(aA + aB, 0.f);
        }
        __syncthreads();

        // phase D: g layer3 (32 -> 3) + relu + residual (state in regs)
        if (t < BN*3) {
            int i = t / 3, d = t % 3;
            float acc = bg3s[s];
            #pragma unroll
            for (int k3 = 0; k3 < 32; k3++)
                acc = fmaf(sA[i*128 + k3], sG3[k3*3 + d], acc);
            float ns = stv + fmaxf(acc, 0.f);
            stv = ns;
            if (s == 2) state[base*3 + t] = ns;    // final output, once
            else        sB[i*128 + d] = ns;        // feed next f phase
        }
        __syncthreads();

        if (s < 2) {
            // ---- MLP_f for step s+1 ----
            #pragma unroll
            for (int j = 0; j < 2; j++) {
                int i = h6*2 + j;
                float acc = bf1[s+1];
                acc = fmaf(sB[i*128+0], w1a[s+1], acc);
                acc = fmaf(sB[i*128+1], w1b[s+1], acc);
                acc = fmaf(sB[i*128+2], w1c[s+1], acc);
                sA[i*128 + k64] = fmaxf(acc, 0.f);
            }
            cpa_wait<1>();        // F2t staged
            __syncthreads();

            float acc2[4];
            #pragma unroll
            for (int j = 0; j < 4; j++) acc2[j] = bf2[s+1];
            {
                const float* Wc = sF2t + c*68;
                #pragma unroll 4
                for (int kk = 0; kk < 64; kk += 4) {
                    float4 w = *(const float4*)(Wc + kk);
                    #pragma unroll
                    for (int j = 0; j < 4; j++) {
                        float4 v = *(const float4*)(sA + (g3c*4 + j)*128 + kk);
                        acc2[j] = fmaf(v.x, w.x, acc2[j]);
                        acc2[j] = fmaf(v.y, w.y, acc2[j]);
                        acc2[j] = fmaf(v.z, w.z, acc2[j]);
                        acc2[j] = fmaf(v.w, w.w, acc2[j]);
                    }
                }
            }
            #pragma unroll
            for (int j = 0; j < 4; j++)
                sB[(g3c*4 + j)*128 + c] = fmaxf(acc2[j], 0.f);
            cpa_wait<0>();        // F3t staged
            __syncthreads();

            float acc3[4];
            #pragma unroll
            for (int j = 0; j < 4; j++) acc3[j] = bf3[s+1];
            {
                const float* Wc = sF3t + c*132;
                #pragma unroll 4
                for (int kk = 0; kk < 128; kk += 4) {
                    float4 w = *(const float4*)(Wc + kk);
                    #pragma unroll
                    for (int j = 0; j < 4; j++) {
                        float4 v = *(const float4*)(sB + (g3c*4 + j)*128 + kk);
                        acc3[j] = fmaf(v.x, w.x, acc3[j]);
                        acc3[j] = fmaf(v.y, w.y, acc3[j]);
                        acc3[j] = fmaf(v.z, w.z, acc3[j]);
                        acc3[j] = fmaf(v.w, w.w, acc3[j]);
                    }
                }
            }
            float* Fo = g_Fbuf[cur ^ 1] + base*128;
            #pragma unroll
            for (int j = 0; j < 4; j++)
                Fo[(g3c*4 + j)*128 + c] = fmaxf(acc3[j], 0.f);

            grid_bar();
            cur ^= 1;
        }
    }
}

// ---------------------------------------------------------------------------
extern "C" void kernel_launch(void* const* d_in, const int* in_sizes, int n_in,
                              void* d_out, int out_size) {
    const float* x   = (const float*)d_in[0];
    const float* fW1 = (const float*)d_in[7];
    const float* fb1 = (const float*)d_in[8];
    const float* fW2 = (const float*)d_in[9];
    const float* fb2 = (const float*)d_in[10];
    const float* fW3 = (const float*)d_in[11];
    const float* fb3 = (const float*)d_in[12];
    const float* gW1 = (const float*)d_in[13];
    const float* gb1 = (const float*)d_in[14];
    const float* gW2 = (const float*)d_in[15];
    const float* gb2 = (const float*)d_in[16];
    const float* gW3 = (const float*)d_in[17];
    const float* gb3 = (const float*)d_in[18];
    float* state = (float*)d_out;

    cudaFuncSetAttribute(pointgnn_persistent,
                         cudaFuncAttributeMaxDynamicSharedMemorySize, SMEM_BYTES);

    pointgnn_persistent<<<GRID, TPB, SMEM_BYTES>>>(x, state,
        fW1, fb1, fW2, fb2, fW3, fb3,
        gW1, gb1, gW2, gb2, gW3, gb3);
}

// round 16
// speedup vs baseline: 1.1701x; 1.1701x over previous
#include <cuda_runtime.h>
#include <cuda_bf16.h>

// PointGNN, algebraically reduced, single persistent kernel, 1 block/SM,
// per-step weights staged via background cp.async into big dynamic smem.
//   adj(i) = { j : |x_i - x_j|^2 < 0.05 }  (fixed; self always in-set)
//   F_t[j]   = MLP_f([0,0,0,state_j])      (per NODE, not per edge)
//   agg_t[i] = max_{j in adj(i)} F_t[j]    (channelwise; F>=0 so 0-floor exact)
//   state   += relu(MLP_g(agg_t))
// h-MLP provably dead. Proven R13 structure (TPB=384, interleaved 4-node max,
// split-k) + u32 pre-scaled byte-offset neighbor lists (kills per-load IMAD).
// Lists padded to MAXD with self (exact under max). g_F double-buffered;
// 3 grid barriers; GRID=128 <= 148 SMs -> 1 co-resident block/SM (barrier safe).

#define MM    384
#define NODES (4*MM)
#define MASKW 12
#define BN    12
#define TPB   384
#define GRID  (NODES/BN)   // 128
#define MAXD  128

// smem: sG1 8192 | sG2 2048 | sF2 8192 | sF3 16384 | sA 1536 | sB 1536
//       | sG3 96 | sN32 1536(u32) | sD 12  => 39,532 floats = 158,128 B
#define SMEM_BYTES (39532*4)

__device__ float    g_Fbuf[2][NODES * 128];
__device__ unsigned g_bar;   // monotonic; wrap-safe barrier

__device__ __forceinline__ void cpa(float* dst, const float* src, int nfloats) {
    for (int idx = threadIdx.x * 4; idx < nfloats; idx += TPB * 4) {
        unsigned sa = (unsigned)__cvta_generic_to_shared(dst + idx);
        asm volatile("cp.async.cg.shared.global [%0], [%1], 16;"
                     :: "r"(sa), "l"(src + idx));
    }
}
__device__ __forceinline__ void cpa_commit() {
    asm volatile("cp.async.commit_group;");
}
template<int N> __device__ __forceinline__ void cpa_wait() {
    asm volatile("cp.async.wait_group %0;" :: "n"(N));
}

// grid-wide barrier: monotonic ticket counter, wrap-safe compare
__device__ __forceinline__ void grid_bar() {
    __syncthreads();
    if (threadIdx.x == 0) {
        __threadfence();
        unsigned v = atomicAdd(&g_bar, 1u);
        unsigned target = v - (v % (unsigned)GRID) + (unsigned)GRID;
        unsigned cur;
        do {
            asm volatile("ld.acquire.gpu.u32 %0, [%1];" : "=r"(cur) : "l"(&g_bar));
        } while ((int)(cur - target) < 0);
    }
    __syncthreads();
}

// ---------------------------------------------------------------------------
__global__ __launch_bounds__(TPB) void pointgnn_persistent(
    const float* x, float* state,
    const float* fW1, const float* fb1, const float* fW2, const float* fb2,
    const float* fW3, const float* fb3,
    const float* gW1, const float* gb1, const float* gW2, const float* gb2,
    const float* gW3, const float* gb3)
{
    extern __shared__ float sm[];
    float*    sG1  = sm;                  // 8192
    float*    sG2  = sG1 + 8192;          // 2048
    float*    sF2  = sG2 + 2048;          // 8192
    float*    sF3  = sF2 + 8192;          // 16384
    float*    sA   = sF3 + 16384;         // 12 x 128
    float*    sB   = sA + 1536;           // 12 x 128
    float*    sG3  = sB + 1536;           // 96
    unsigned* sN32 = (unsigned*)(sG3 + 96);   // 12 x 128 u32 byte offsets
    int*      sD   = (int*)(sN32 + BN*MAXD);  // 12

    const int t    = threadIdx.x;
    const int base = blockIdx.x * BN;     // 12 nodes, same batch (384%12==0)
    const int n    = base / MM;
    const int c    = t & 127;             // channel lane
    const int g3c  = t >> 7;              // 0..2 -> node quad
    const int k64  = t & 63;
    const int h6   = t >> 6;              // 0..5 -> node pair

    // ---- stage f0 weights immediately (overlap adjacency build) ----
    cpa(sF2, fW2, 8192);  cpa_commit();   // group: F2
    cpa(sF3, fW3, 16384); cpa_commit();   // group: F3

    // ---- one-time prefetch: all 3 steps' biases + state + fW1 rows ----
    float bf1[3], bf2[3], bf3[3], bg1[3], bg2[3], bg3s[3];
    float w1a[3], w1b[3], w1c[3];
    #pragma unroll
    for (int s = 0; s < 3; s++) {
        bf1[s] = fb1[s*64  + k64];
        bf2[s] = fb2[s*128 + c];
        bf3[s] = fb3[s*128 + c];
        bg1[s] = gb1[s*64  + k64];
        bg2[s] = gb2[s*32  + (t & 31)];
        w1a[s] = fW1[s*384 + 3*64 + k64];
        w1b[s] = fW1[s*384 + 4*64 + k64];
        w1c[s] = fW1[s*384 + 5*64 + k64];
    }
    float stv = 0.f;
    if (t < BN*3) {
        stv = x[base*3 + t];
        #pragma unroll
        for (int s = 0; s < 3; s++) bg3s[s] = gb3[s*3 + t % 3];
    }

    // ---- adjacency (once): warp-per-node popc compaction; u32 byte offsets
    //      (j*512); lists padded to MAXD with self (exact under max) ----
    {
        const int warp = t >> 5, lane = t & 31;   // 12 warps = 12 nodes
        const int i = base + warp;
        float xi0 = x[i*3+0], xi1 = x[i*3+1], xi2 = x[i*3+2];
        int cnt = 0;
        #pragma unroll
        for (int wc = 0; wc < MASKW; wc++) {
            int j = wc*32 + lane;
            const float* xj = x + (n*MM + j)*3;
            float dx = xi0 - xj[0], dy = xi1 - xj[1], dz = xi2 - xj[2];
            // non-contracted to match reference's (diff*diff).sum() compare
            float s2 = __fadd_rn(__fadd_rn(__fmul_rn(dx,dx), __fmul_rn(dy,dy)),
                                 __fmul_rn(dz,dz));
            bool pred = s2 < 0.05f;
            unsigned m = __ballot_sync(0xffffffffu, pred);
            int pos = cnt + __popc(m & ((1u << lane) - 1u));
            if (pred && pos < MAXD) sN32[warp*MAXD + pos] = (unsigned)(j*512);
            cnt += __popc(m);
        }
        int cl = cnt < MAXD ? cnt : MAXD;
        unsigned selfoff = (unsigned)((i - n*MM)*512);
        for (int p = cl + lane; p < MAXD; p += 32) sN32[warp*MAXD + p] = selfoff;
        if (lane == 0) sD[warp] = (cl + 7) & ~7;
    }
    if (t < BN*3) sB[(t/3)*128 + t%3] = stv;       // state := x
    __syncthreads();

    // ================= F0 = MLP_f(x) =================
    {
        // layer1 (rows 3..5 only, weights in regs)
        #pragma unroll
        for (int j = 0; j < 2; j++) {
            int i = h6*2 + j;
            float acc = bf1[0];
            acc = fmaf(sB[i*128+0], w1a[0], acc);
            acc = fmaf(sB[i*128+1], w1b[0], acc);
            acc = fmaf(sB[i*128+2], w1c[0], acc);
            sA[i*128 + k64] = fmaxf(acc, 0.f);
        }
        cpa_wait<1>();        // F2 staged (F3 may still be in flight)
        __syncthreads();

        // layer2: 64 -> 128, ILP-4
        float acc2[4];
        #pragma unroll
        for (int j = 0; j < 4; j++) acc2[j] = bf2[0];
        #pragma unroll 4
        for (int kk = 0; kk < 64; kk++) {
            float w = sF2[kk*128 + c];
            #pragma unroll
            for (int j = 0; j < 4; j++)
                acc2[j] = fmaf(sA[(g3c*4 + j)*128 + kk], w, acc2[j]);
        }
        #pragma unroll
        for (int j = 0; j < 4; j++) sB[(g3c*4 + j)*128 + c] = fmaxf(acc2[j], 0.f);
        cpa_wait<0>();        // F3 staged
        __syncthreads();

        // layer3: 128 -> 128 single pass, split-k: 4 nodes x 2 partials
        float accA[4], accB[4];
        #pragma unroll
        for (int j = 0; j < 4; j++) { accA[j] = bf3[0]; accB[j] = 0.f; }
        #pragma unroll 4
        for (int kk = 0; kk < 64; kk++) {
            float wA = sF3[kk*128 + c];
            float wB = sF3[(kk+64)*128 + c];
            #pragma unroll
            for (int j = 0; j < 4; j++) {
                accA[j] = fmaf(sB[(g3c*4 + j)*128 + kk],      wA, accA[j]);
                accB[j] = fmaf(sB[(g3c*4 + j)*128 + kk + 64], wB, accB[j]);
            }
        }
        float* F0 = g_Fbuf[0] + base*128;
        #pragma unroll
        for (int j = 0; j < 4; j++)
            F0[(g3c*4 + j)*128 + c] = fmaxf(accA[j] + accB[j], 0.f);
    }
    grid_bar();

    // ================= 3 timesteps =================
    int cur = 0;
    #pragma unroll
    for (int s = 0; s < 3; s++) {
        // stage this step's weights in the background (first-use order)
        cpa(sG1, gW1 + s*8192, 8192);
        cpa(sG2, gW2 + s*2048, 2048);
        cpa_commit();                               // group G
        if (s < 2) {
            cpa(sF2, fW2 + (s+1)*8192, 8192);  cpa_commit();   // group F2
            cpa(sF3, fW3 + (s+1)*16384, 16384); cpa_commit();  // group F3
        }
        if (t < 96) sG3[t] = gW3[s*96 + t];

        // phase A: channelwise max, 4 nodes interleaved -> 32 loads in flight,
        //          byte-offset addressing (single IADD per load)
        {
            const char* FnC = (const char*)(g_Fbuf[cur] + n*MM*128) + c*4;
            const int i0 = g3c*4;
            int dgq = sD[i0];
            dgq = max(dgq, sD[i0+1]); dgq = max(dgq, sD[i0+2]); dgq = max(dgq, sD[i0+3]);
            float mx[4] = {0.f, 0.f, 0.f, 0.f};
            for (int d = 0; d < dgq; d += 8) {
                float v[4][8];
                #pragma unroll
                for (int j = 0; j < 4; j++) {
                    const unsigned* Ni = sN32 + (i0 + j)*MAXD + d;
                    #pragma unroll
                    for (int e = 0; e < 8; e++)
                        v[j][e] = *(const float*)(FnC + Ni[e]);
                }
                #pragma unroll
                for (int j = 0; j < 4; j++) {
                    float m01 = fmaxf(v[j][0], v[j][1]), m23 = fmaxf(v[j][2], v[j][3]);
                    float m45 = fmaxf(v[j][4], v[j][5]), m67 = fmaxf(v[j][6], v[j][7]);
                    mx[j] = fmaxf(mx[j], fmaxf(fmaxf(m01, m23), fmaxf(m45, m67)));
                }
            }
            #pragma unroll
            for (int j = 0; j < 4; j++) sA[(i0 + j)*128 + c] = mx[j];
        }
        if (s < 2) cpa_wait<2>(); else cpa_wait<0>();   // g-weights staged
        __syncthreads();

        // phase B: g layer1 (128 -> 64), 2 nodes x 2 split-k partials
        {
            float a0A = bg1[s], a0B = 0.f, a1A = bg1[s], a1B = 0.f;
            const float* A0 = sA + (h6*2)*128, * A1 = A0 + 128;
            #pragma unroll 8
            for (int d = 0; d < 64; d++) {
                float wA = sG1[d*64 + k64];
                float wB = sG1[(d+64)*64 + k64];
                a0A = fmaf(A0[d],      wA, a0A);
                a0B = fmaf(A0[d + 64], wB, a0B);
                a1A = fmaf(A1[d],      wA, a1A);
                a1B = fmaf(A1[d + 64], wB, a1B);
            }
            sB[(h6*2    )*128 + k64] = fmaxf(a0A + a0B, 0.f);
            sB[(h6*2 + 1)*128 + k64] = fmaxf(a1A + a1B, 0.f);
        }
        __syncthreads();

        // phase C: g layer2 (64 -> 32), split-k 2 partials
        {
            int k2 = t & 31, i12 = t >> 5;
            float aA = bg2[s], aB = 0.f;
            const float* Bi = sB + i12*128;
            #pragma unroll 8
            for (int d = 0; d < 32; d++) {
                aA = fmaf(Bi[d],      sG2[d*32 + k2],      aA);
                aB = fmaf(Bi[d + 32], sG2[(d+32)*32 + k2], aB);
            }
            sA[i12*128 + k2] = fmaxf(aA + aB, 0.f);
        }
        __syncthreads();

        // phase D: g layer3 (32 -> 3) + relu + residual (state in regs)
        if (t < BN*3) {
            int i = t / 3, d = t % 3;
            float acc = bg3s[s];
            #pragma unroll
            for (int k3 = 0; k3 < 32; k3++)
                acc = fmaf(sA[i*128 + k3], sG3[k3*3 + d], acc);
            float ns = stv + fmaxf(acc, 0.f);
            stv = ns;
            if (s == 2) state[base*3 + t] = ns;    // final output, once
            else        sB[i*128 + d] = ns;        // feed next f phase
        }
        __syncthreads();

        if (s < 2) {
            // ---- MLP_f for step s+1 ----
            #pragma unroll
            for (int j = 0; j < 2; j++) {
                int i = h6*2 + j;
                float acc = bf1[s+1];
                acc = fmaf(sB[i*128+0], w1a[s+1], acc);
                acc = fmaf(sB[i*128+1], w1b[s+1], acc);
                acc = fmaf(sB[i*128+2], w1c[s+1], acc);
                sA[i*128 + k64] = fmaxf(acc, 0.f);
            }
            cpa_wait<1>();        // F2 staged
            __syncthreads();

            float acc2[4];
            #pragma unroll
            for (int j = 0; j < 4; j++) acc2[j] = bf2[s+1];
            #pragma unroll 4
            for (int kk = 0; kk < 64; kk++) {
                float w = sF2[kk*128 + c];
                #pragma unroll
                for (int j = 0; j < 4; j++)
                    acc2[j] = fmaf(sA[(g3c*4 + j)*128 + kk], w, acc2[j]);
            }
            #pragma unroll
            for (int j = 0; j < 4; j++)
                sB[(g3c*4 + j)*128 + c] = fmaxf(acc2[j], 0.f);
            cpa_wait<0>();        // F3 staged
            __syncthreads();

            // layer3 split-k: 4 nodes x 2 partials
            float accA[4], accB[4];
            #pragma unroll
            for (int j = 0; j < 4; j++) { accA[j] = bf3[s+1]; accB[j] = 0.f; }
            #pragma unroll 4
            for (int kk = 0; kk < 64; kk++) {
                float wA = sF3[kk*128 + c];
                float wB = sF3[(kk+64)*128 + c];
                #pragma unroll
                for (int j = 0; j < 4; j++) {
                    accA[j] = fmaf(sB[(g3c*4 + j)*128 + kk],      wA, accA[j]);
                    accB[j] = fmaf(sB[(g3c*4 + j)*128 + kk + 64], wB, accB[j]);
                }
            }
            float* Fo = g_Fbuf[cur ^ 1] + base*128;
            #pragma unroll
            for (int j = 0; j < 4; j++)
                Fo[(g3c*4 + j)*128 + c] = fmaxf(accA[j] + accB[j], 0.f);

            grid_bar();
            cur ^= 1;
        }
    }
}

// ---------------------------------------------------------------------------
extern "C" void kernel_launch(void* const* d_in, const int* in_sizes, int n_in,
                              void* d_out, int out_size) {
    const float* x   = (const float*)d_in[0];
    const float* fW1 = (const float*)d_in[7];
    const float* fb1 = (const float*)d_in[8];
    const float* fW2 = (const float*)d_in[9];
    const float* fb2 = (const float*)d_in[10];
    const float* fW3 = (const float*)d_in[11];
    const float* fb3 = (const float*)d_in[12];
    const float* gW1 = (const float*)d_in[13];
    const float* gb1 = (const float*)d_in[14];
    const float* gW2 = (const float*)d_in[15];
    const float* gb2 = (const float*)d_in[16];
    const float* gW3 = (const float*)d_in[17];
    const float* gb3 = (const float*)d_in[18];
    float* state = (float*)d_out;

    cudaFuncSetAttribute(pointgnn_persistent,
                         cudaFuncAttributeMaxDynamicSharedMemorySize, SMEM_BYTES);

    pointgnn_persistent<<<GRID, TPB, SMEM_BYTES>>>(x, state,
        fW1, fb1, fW2, fb2, fW3, fb3,
        gW1, gb1, gW2, gb2, gW3, gb3);
}

// round 17
// speedup vs baseline: 1.2216x; 1.0440x over previous
#include <cuda_runtime.h>
#include <cuda_bf16.h>

// PointGNN, algebraically reduced, single persistent kernel, 1 block/SM,
// per-step weights staged via background cp.async into big dynamic smem.
//   adj(i) = { j : |x_i - x_j|^2 < 0.05 }  (fixed; self always in-set)
//   F_t[j]   = MLP_f([0,0,0,state_j])      (per NODE, not per edge)
//   agg_t[i] = max_{j in adj(i)} F_t[j]    (channelwise; F>=0 so 0-floor exact)
//   state   += relu(MLP_g(agg_t))
// h-MLP provably dead. R16 structure (TPB=384, interleaved 4-node max,
// split-k, u32 byte-offset lists) + float4 BROADCAST activation loads:
// row indices (g3c/h6/i12) are warp-uniform -> LDS.128 broadcast is
// conflict-free and replaces 4 scalar LDS. GRID=128 <= 148 SMs -> 1 block/SM.

#define MM    384
#define NODES (4*MM)
#define MASKW 12
#define BN    12
#define TPB   384
#define GRID  (NODES/BN)   // 128
#define MAXD  128

// smem: sG1 8192 | sG2 2048 | sF2 8192 | sF3 16384 | sA 1536 | sB 1536
//       | sG3 96 | sN32 1536(u32) | sD 12  => 39,532 floats = 158,128 B
#define SMEM_BYTES (39532*4)

__device__ float    g_Fbuf[2][NODES * 128];
__device__ unsigned g_bar;   // monotonic; wrap-safe barrier

__device__ __forceinline__ void cpa(float* dst, const float* src, int nfloats) {
    for (int idx = threadIdx.x * 4; idx < nfloats; idx += TPB * 4) {
        unsigned sa = (unsigned)__cvta_generic_to_shared(dst + idx);
        asm volatile("cp.async.cg.shared.global [%0], [%1], 16;"
                     :: "r"(sa), "l"(src + idx));
    }
}
__device__ __forceinline__ void cpa_commit() {
    asm volatile("cp.async.commit_group;");
}
template<int N> __device__ __forceinline__ void cpa_wait() {
    asm volatile("cp.async.wait_group %0;" :: "n"(N));
}

// grid-wide barrier: monotonic ticket counter, wrap-safe compare
__device__ __forceinline__ void grid_bar() {
    __syncthreads();
    if (threadIdx.x == 0) {
        __threadfence();
        unsigned v = atomicAdd(&g_bar, 1u);
        unsigned target = v - (v % (unsigned)GRID) + (unsigned)GRID;
        unsigned cur;
        do {
            asm volatile("ld.acquire.gpu.u32 %0, [%1];" : "=r"(cur) : "l"(&g_bar));
        } while ((int)(cur - target) < 0);
    }
    __syncthreads();
}

// ---------------------------------------------------------------------------
__global__ __launch_bounds__(TPB) void pointgnn_persistent(
    const float* x, float* state,
    const float* fW1, const float* fb1, const float* fW2, const float* fb2,
    const float* fW3, const float* fb3,
    const float* gW1, const float* gb1, const float* gW2, const float* gb2,
    const float* gW3, const float* gb3)
{
    extern __shared__ float sm[];
    float*    sG1  = sm;                  // 8192
    float*    sG2  = sG1 + 8192;          // 2048
    float*    sF2  = sG2 + 2048;          // 8192
    float*    sF3  = sF2 + 8192;          // 16384
    float*    sA   = sF3 + 16384;         // 12 x 128
    float*    sB   = sA + 1536;           // 12 x 128
    float*    sG3  = sB + 1536;           // 96
    unsigned* sN32 = (unsigned*)(sG3 + 96);   // 12 x 128 u32 byte offsets
    int*      sD   = (int*)(sN32 + BN*MAXD);  // 12

    const int t    = threadIdx.x;
    const int base = blockIdx.x * BN;     // 12 nodes, same batch (384%12==0)
    const int n    = base / MM;
    const int c    = t & 127;             // channel lane
    const int g3c  = t >> 7;              // 0..2 -> node quad (warp-uniform)
    const int k64  = t & 63;
    const int h6   = t >> 6;              // 0..5 -> node pair (warp-uniform)

    // ---- stage f0 weights immediately (overlap adjacency build) ----
    cpa(sF2, fW2, 8192);  cpa_commit();   // group: F2
    cpa(sF3, fW3, 16384); cpa_commit();   // group: F3

    // ---- one-time prefetch: all 3 steps' biases + state + fW1 rows ----
    float bf1[3], bf2[3], bf3[3], bg1[3], bg2[3], bg3s[3];
    float w1a[3], w1b[3], w1c[3];
    #pragma unroll
    for (int s = 0; s < 3; s++) {
        bf1[s] = fb1[s*64  + k64];
        bf2[s] = fb2[s*128 + c];
        bf3[s] = fb3[s*128 + c];
        bg1[s] = gb1[s*64  + k64];
        bg2[s] = gb2[s*32  + (t & 31)];
        w1a[s] = fW1[s*384 + 3*64 + k64];
        w1b[s] = fW1[s*384 + 4*64 + k64];
        w1c[s] = fW1[s*384 + 5*64 + k64];
    }
    float stv = 0.f;
    if (t < BN*3) {
        stv = x[base*3 + t];
        #pragma unroll
        for (int s = 0; s < 3; s++) bg3s[s] = gb3[s*3 + t % 3];
    }

    // ---- adjacency (once): warp-per-node popc compaction; u32 byte offsets
    //      (j*512); lists padded to MAXD with self (exact under max) ----
    {
        const int warp = t >> 5, lane = t & 31;   // 12 warps = 12 nodes
        const int i = base + warp;
        float xi0 = x[i*3+0], xi1 = x[i*3+1], xi2 = x[i*3+2];
        int cnt = 0;
        #pragma unroll
        for (int wc = 0; wc < MASKW; wc++) {
            int j = wc*32 + lane;
            const float* xj = x + (n*MM + j)*3;
            float dx = xi0 - xj[0], dy = xi1 - xj[1], dz = xi2 - xj[2];
            // non-contracted to match reference's (diff*diff).sum() compare
            float s2 = __fadd_rn(__fadd_rn(__fmul_rn(dx,dx), __fmul_rn(dy,dy)),
                                 __fmul_rn(dz,dz));
            bool pred = s2 < 0.05f;
            unsigned m = __ballot_sync(0xffffffffu, pred);
            int pos = cnt + __popc(m & ((1u << lane) - 1u));
            if (pred && pos < MAXD) sN32[warp*MAXD + pos] = (unsigned)(j*512);
            cnt += __popc(m);
        }
        int cl = cnt < MAXD ? cnt : MAXD;
        unsigned selfoff = (unsigned)((i - n*MM)*512);
        for (int p = cl + lane; p < MAXD; p += 32) sN32[warp*MAXD + p] = selfoff;
        if (lane == 0) sD[warp] = (cl + 7) & ~7;
    }
    if (t < BN*3) sB[(t/3)*128 + t%3] = stv;       // state := x
    __syncthreads();

    // ================= F0 = MLP_f(x) =================
    {
        // layer1 (rows 3..5 only, weights in regs)
        #pragma unroll
        for (int j = 0; j < 2; j++) {
            int i = h6*2 + j;
            float acc = bf1[0];
            acc = fmaf(sB[i*128+0], w1a[0], acc);
            acc = fmaf(sB[i*128+1], w1b[0], acc);
            acc = fmaf(sB[i*128+2], w1c[0], acc);
            sA[i*128 + k64] = fmaxf(acc, 0.f);
        }
        cpa_wait<1>();        // F2 staged (F3 may still be in flight)
        __syncthreads();

        // layer2: 64 -> 128, ILP-4, float4 broadcast act loads
        float acc2[4];
        #pragma unroll
        for (int j = 0; j < 4; j++) acc2[j] = bf2[0];
        #pragma unroll 2
        for (int kk = 0; kk < 64; kk += 4) {
            float w0 = sF2[(kk+0)*128 + c], w1 = sF2[(kk+1)*128 + c];
            float w2 = sF2[(kk+2)*128 + c], w3 = sF2[(kk+3)*128 + c];
            #pragma unroll
            for (int j = 0; j < 4; j++) {
                float4 v = *(const float4*)(sA + (g3c*4 + j)*128 + kk);
                acc2[j] = fmaf(v.x, w0, acc2[j]);
                acc2[j] = fmaf(v.y, w1, acc2[j]);
                acc2[j] = fmaf(v.z, w2, acc2[j]);
                acc2[j] = fmaf(v.w, w3, acc2[j]);
            }
        }
        #pragma unroll
        for (int j = 0; j < 4; j++) sB[(g3c*4 + j)*128 + c] = fmaxf(acc2[j], 0.f);
        cpa_wait<0>();        // F3 staged
        __syncthreads();

        // layer3: 128 -> 128, split-k 2, float4 broadcast act loads
        float accA[4], accB[4];
        #pragma unroll
        for (int j = 0; j < 4; j++) { accA[j] = bf3[0]; accB[j] = 0.f; }
        #pragma unroll 2
        for (int kk = 0; kk < 64; kk += 4) {
            float wA0 = sF3[(kk+0)*128 + c], wA1 = sF3[(kk+1)*128 + c];
            float wA2 = sF3[(kk+2)*128 + c], wA3 = sF3[(kk+3)*128 + c];
            float wB0 = sF3[(kk+64)*128 + c], wB1 = sF3[(kk+65)*128 + c];
            float wB2 = sF3[(kk+66)*128 + c], wB3 = sF3[(kk+67)*128 + c];
            #pragma unroll
            for (int j = 0; j < 4; j++) {
                const float* Bj = sB + (g3c*4 + j)*128;
                float4 vA = *(const float4*)(Bj + kk);
                float4 vB = *(const float4*)(Bj + kk + 64);
                accA[j] = fmaf(vA.x, wA0, accA[j]);
                accA[j] = fmaf(vA.y, wA1, accA[j]);
                accA[j] = fmaf(vA.z, wA2, accA[j]);
                accA[j] = fmaf(vA.w, wA3, accA[j]);
                accB[j] = fmaf(vB.x, wB0, accB[j]);
                accB[j] = fmaf(vB.y, wB1, accB[j]);
                accB[j] = fmaf(vB.z, wB2, accB[j]);
                accB[j] = fmaf(vB.w, wB3, accB[j]);
            }
        }
        float* F0 = g_Fbuf[0] + base*128;
        #pragma unroll
        for (int j = 0; j < 4; j++)
            F0[(g3c*4 + j)*128 + c] = fmaxf(accA[j] + accB[j], 0.f);
    }
    grid_bar();

    // ================= 3 timesteps =================
    int cur = 0;
    #pragma unroll
    for (int s = 0; s < 3; s++) {
        // stage this step's weights in the background (first-use order)
        cpa(sG1, gW1 + s*8192, 8192);
        cpa(sG2, gW2 + s*2048, 2048);
        cpa_commit();                               // group G
        if (s < 2) {
            cpa(sF2, fW2 + (s+1)*8192, 8192);  cpa_commit();   // group F2
            cpa(sF3, fW3 + (s+1)*16384, 16384); cpa_commit();  // group F3
        }
        if (t < 96) sG3[t] = gW3[s*96 + t];

        // phase A: channelwise max, 4 nodes interleaved -> 32 loads in flight,
        //          byte-offset addressing (single IADD per load)
        {
            const char* FnC = (const char*)(g_Fbuf[cur] + n*MM*128) + c*4;
            const int i0 = g3c*4;
            int dgq = sD[i0];
            dgq = max(dgq, sD[i0+1]); dgq = max(dgq, sD[i0+2]); dgq = max(dgq, sD[i0+3]);
            float mx[4] = {0.f, 0.f, 0.f, 0.f};
            for (int d = 0; d < dgq; d += 8) {
                float v[4][8];
                #pragma unroll
                for (int j = 0; j < 4; j++) {
                    const unsigned* Ni = sN32 + (i0 + j)*MAXD + d;
                    #pragma unroll
                    for (int e = 0; e < 8; e++)
                        v[j][e] = *(const float*)(FnC + Ni[e]);
                }
                #pragma unroll
                for (int j = 0; j < 4; j++) {
                    float m01 = fmaxf(v[j][0], v[j][1]), m23 = fmaxf(v[j][2], v[j][3]);
                    float m45 = fmaxf(v[j][4], v[j][5]), m67 = fmaxf(v[j][6], v[j][7]);
                    mx[j] = fmaxf(mx[j], fmaxf(fmaxf(m01, m23), fmaxf(m45, m67)));
                }
            }
            #pragma unroll
            for (int j = 0; j < 4; j++) sA[(i0 + j)*128 + c] = mx[j];
        }
        if (s < 2) cpa_wait<2>(); else cpa_wait<0>();   // g-weights staged
        __syncthreads();

        // phase B: g layer1 (128 -> 64), 2 nodes x 2 split-k, float4 bcast acts
        {
            float a0A = bg1[s], a0B = 0.f, a1A = bg1[s], a1B = 0.f;
            const float* A0 = sA + (h6*2)*128, * A1 = A0 + 128;
            #pragma unroll 2
            for (int d = 0; d < 64; d += 4) {
                float wA0 = sG1[(d+0)*64 + k64], wA1 = sG1[(d+1)*64 + k64];
                float wA2 = sG1[(d+2)*64 + k64], wA3 = sG1[(d+3)*64 + k64];
                float wB0 = sG1[(d+64)*64 + k64], wB1 = sG1[(d+65)*64 + k64];
                float wB2 = sG1[(d+66)*64 + k64], wB3 = sG1[(d+67)*64 + k64];
                float4 vA0 = *(const float4*)(A0 + d);
                float4 vB0 = *(const float4*)(A0 + d + 64);
                float4 vA1 = *(const float4*)(A1 + d);
                float4 vB1 = *(const float4*)(A1 + d + 64);
                a0A = fmaf(vA0.x, wA0, a0A); a0A = fmaf(vA0.y, wA1, a0A);
                a0A = fmaf(vA0.z, wA2, a0A); a0A = fmaf(vA0.w, wA3, a0A);
                a0B = fmaf(vB0.x, wB0, a0B); a0B = fmaf(vB0.y, wB1, a0B);
                a0B = fmaf(vB0.z, wB2, a0B); a0B = fmaf(vB0.w, wB3, a0B);
                a1A = fmaf(vA1.x, wA0, a1A); a1A = fmaf(vA1.y, wA1, a1A);
                a1A = fmaf(vA1.z, wA2, a1A); a1A = fmaf(vA1.w, wA3, a1A);
                a1B = fmaf(vB1.x, wB0, a1B); a1B = fmaf(vB1.y, wB1, a1B);
                a1B = fmaf(vB1.z, wB2, a1B); a1B = fmaf(vB1.w, wB3, a1B);
            }
            sB[(h6*2    )*128 + k64] = fmaxf(a0A + a0B, 0.f);
            sB[(h6*2 + 1)*128 + k64] = fmaxf(a1A + a1B, 0.f);
        }
        __syncthreads();

        // phase C: g layer2 (64 -> 32), split-k 2, float4 bcast acts
        {
            int k2 = t & 31, i12 = t >> 5;   // i12 warp-uniform
            float aA = bg2[s], aB = 0.f;
            const float* Bi = sB + i12*128;
            #pragma unroll
            for (int d = 0; d < 32; d += 4) {
                float wA0 = sG2[(d+0)*32 + k2], wA1 = sG2[(d+1)*32 + k2];
                float wA2 = sG2[(d+2)*32 + k2], wA3 = sG2[(d+3)*32 + k2];
                float wB0 = sG2[(d+32)*32 + k2], wB1 = sG2[(d+33)*32 + k2];
                float wB2 = sG2[(d+34)*32 + k2], wB3 = sG2[(d+35)*32 + k2];
                float4 vA = *(const float4*)(Bi + d);
                float4 vB = *(const float4*)(Bi + d + 32);
                aA = fmaf(vA.x, wA0, aA); aA = fmaf(vA.y, wA1, aA);
                aA = fmaf(vA.z, wA2, aA); aA = fmaf(vA.w, wA3, aA);
                aB = fmaf(vB.x, wB0, aB); aB = fmaf(vB.y, wB1, aB);
                aB = fmaf(vB.z, wB2, aB); aB = fmaf(vB.w, wB3, aB);
            }
            sA[i12*128 + k2] = fmaxf(aA + aB, 0.f);
        }
        __syncthreads();

        // phase D: g layer3 (32 -> 3) + relu + residual (state in regs)
        if (t < BN*3) {
            int i = t / 3, d = t % 3;
            float acc = bg3s[s];
            #pragma unroll
            for (int k3 = 0; k3 < 32; k3++)
                acc = fmaf(sA[i*128 + k3], sG3[k3*3 + d], acc);
            float ns = stv + fmaxf(acc, 0.f);
            stv = ns;
            if (s == 2) state[base*3 + t] = ns;    // final output, once
            else        sB[i*128 + d] = ns;        // feed next f phase
        }
        __syncthreads();

        if (s < 2) {
            // ---- MLP_f for step s+1 ----
            #pragma unroll
            for (int j = 0; j < 2; j++) {
                int i = h6*2 + j;
                float acc = bf1[s+1];
                acc = fmaf(sB[i*128+0], w1a[s+1], acc);
                acc = fmaf(sB[i*128+1], w1b[s+1], acc);
                acc = fmaf(sB[i*128+2], w1c[s+1], acc);
                sA[i*128 + k64] = fmaxf(acc, 0.f);
            }
            cpa_wait<1>();        // F2 staged
            __syncthreads();

            float acc2[4];
            #pragma unroll
            for (int j = 0; j < 4; j++) acc2[j] = bf2[s+1];
            #pragma unroll 2
            for (int kk = 0; kk < 64; kk += 4) {
                float w0 = sF2[(kk+0)*128 + c], w1 = sF2[(kk+1)*128 + c];
                float w2 = sF2[(kk+2)*128 + c], w3 = sF2[(kk+3)*128 + c];
                #pragma unroll
                for (int j = 0; j < 4; j++) {
                    float4 v = *(const float4*)(sA + (g3c*4 + j)*128 + kk);
                    acc2[j] = fmaf(v.x, w0, acc2[j]);
                    acc2[j] = fmaf(v.y, w1, acc2[j]);
                    acc2[j] = fmaf(v.z, w2, acc2[j]);
                    acc2[j] = fmaf(v.w, w3, acc2[j]);
                }
            }
            #pragma unroll
            for (int j = 0; j < 4; j++)
                sB[(g3c*4 + j)*128 + c] = fmaxf(acc2[j], 0.f);
            cpa_wait<0>();        // F3 staged
            __syncthreads();

            float accA[4], accB[4];
            #pragma unroll
            for (int j = 0; j < 4; j++) { accA[j] = bf3[s+1]; accB[j] = 0.f; }
            #pragma unroll 2
            for (int kk = 0; kk < 64; kk += 4) {
                float wA0 = sF3[(kk+0)*128 + c], wA1 = sF3[(kk+1)*128 + c];
                float wA2 = sF3[(kk+2)*128 + c], wA3 = sF3[(kk+3)*128 + c];
                float wB0 = sF3[(kk+64)*128 + c], wB1 = sF3[(kk+65)*128 + c];
                float wB2 = sF3[(kk+66)*128 + c], wB3 = sF3[(kk+67)*128 + c];
                #pragma unroll
                for (int j = 0; j < 4; j++) {
                    const float* Bj = sB + (g3c*4 + j)*128;
                    float4 vA = *(const float4*)(Bj + kk);
                    float4 vB = *(const float4*)(Bj + kk + 64);
                    accA[j] = fmaf(vA.x, wA0, accA[j]);
                    accA[j] = fmaf(vA.y, wA1, accA[j]);
                    accA[j] = fmaf(vA.z, wA2, accA[j]);
                    accA[j] = fmaf(vA.w, wA3, accA[j]);
                    accB[j] = fmaf(vB.x, wB0, accB[j]);
                    accB[j] = fmaf(vB.y, wB1, accB[j]);
                    accB[j] = fmaf(vB.z, wB2, accB[j]);
                    accB[j] = fmaf(vB.w, wB3, accB[j]);
                }
            }
            float* Fo = g_Fbuf[cur ^ 1] + base*128;
            #pragma unroll
            for (int j = 0; j < 4; j++)
                Fo[(g3c*4 + j)*128 + c] = fmaxf(accA[j] + accB[j], 0.f);

            grid_bar();
            cur ^= 1;
        }
    }
}

// ---------------------------------------------------------------------------
extern "C" void kernel_launch(void* const* d_in, const int* in_sizes, int n_in,
                              void* d_out, int out_size) {
    const float* x   = (const float*)d_in[0];
    const float* fW1 = (const float*)d_in[7];
    const float* fb1 = (const float*)d_in[8];
    const float* fW2 = (const float*)d_in[9];
    const float* fb2 = (const float*)d_in[10];
    const float* fW3 = (const float*)d_in[11];
    const float* fb3 = (const float*)d_in[12];
    const float* gW1 = (const float*)d_in[13];
    const float* gb1 = (const float*)d_in[14];
    const float* gW2 = (const float*)d_in[15];
    const float* gb2 = (const float*)d_in[16];
    const float* gW3 = (const float*)d_in[17];
    const float* gb3 = (const float*)d_in[18];
    float* state = (float*)d_out;

    cudaFuncSetAttribute(pointgnn_persistent,
                         cudaFuncAttributeMaxDynamicSharedMemorySize, SMEM_BYTES);

    pointgnn_persistent<<<GRID, TPB, SMEM_BYTES>>>(x, state,
        fW1, fb1, fW2, fb2, fW3, fb3,
        gW1, gb1, gW2, gb2, gW3, gb3);
}